// round 9
// baseline (speedup 1.0000x reference)
#include <cuda_runtime.h>
#include <cuda_bf16.h>
#include <math.h>
#include <stdint.h>

// ===================== scratch (static device arrays) ========================
__device__ __nv_bfloat16 g_xh[4096UL * 512],    g_xl[4096UL * 512];
__device__ __nv_bfloat16 g_Wsh[1536UL * 512],   g_Wsl[1536UL * 512];
__device__ __nv_bfloat16 g_Wmh[12288UL * 1536], g_Wml[12288UL * 1536];
__device__ float         g_Wmf[12288UL * 1536];
__device__ __nv_bfloat16 g_Wrh[512UL * 4096],   g_Wrl[512UL * 4096];
__device__ __nv_bfloat16 g_h1h[4096UL * 1536],  g_h1l[4096UL * 1536];
__device__ float         g_h1f[4096UL * 1536];
__device__ __nv_bfloat16 g_h2h[4096UL * 12288], g_h2l[4096UL * 12288];
__device__ float         g_h2f[4096UL * 12288];
__device__ float         g_sc [16UL * 2048 * 2048];
__device__ __nv_bfloat16 g_Ph [16UL * 2048 * 2048], g_Pl[16UL * 2048 * 2048];
__device__ __nv_bfloat16 g_Vth[16UL * 512 * 2048],  g_Vtl[16UL * 512 * 2048];
__device__ __nv_bfloat16 g_aph[4096UL * 4096],  g_apl[4096UL * 4096];

// ===================== helpers (base-target PTX only) ========================
__device__ __forceinline__ uint32_t smem_u32(const void* p) {
    uint32_t a;
    asm("{ .reg .u64 t; cvta.to.shared.u64 t, %1; cvt.u32.u64 %0, t; }"
        : "=r"(a) : "l"(p));
    return a;
}

__device__ __forceinline__ void cp16(uint32_t s, const void* g) {
    asm volatile("cp.async.cg.shared.global [%0], [%1], 16;"
                 :: "r"(s), "l"(g) : "memory");
}

__device__ __forceinline__ void ldsm4(uint32_t* r, uint32_t addr) {
    asm volatile("ldmatrix.sync.aligned.m8n8.x4.shared.b16 {%0,%1,%2,%3}, [%4];"
                 : "=r"(r[0]), "=r"(r[1]), "=r"(r[2]), "=r"(r[3]) : "r"(addr));
}

__device__ __forceinline__ void mma_bf16(float* c, const uint32_t* a, const uint32_t* b) {
    asm volatile(
        "mma.sync.aligned.m16n8k16.row.col.f32.bf16.bf16.f32 "
        "{%0,%1,%2,%3}, {%4,%5,%6,%7}, {%8,%9}, {%0,%1,%2,%3};"
        : "+f"(c[0]), "+f"(c[1]), "+f"(c[2]), "+f"(c[3])
        : "r"(a[0]), "r"(a[1]), "r"(a[2]), "r"(a[3]), "r"(b[0]), "r"(b[1]));
}

__device__ __forceinline__ void mma_tf32(float* c, const uint32_t* a, const uint32_t* b) {
    asm volatile(
        "mma.sync.aligned.m16n8k8.row.col.f32.tf32.tf32.f32 "
        "{%0,%1,%2,%3}, {%4,%5,%6,%7}, {%8,%9}, {%0,%1,%2,%3};"
        : "+f"(c[0]), "+f"(c[1]), "+f"(c[2]), "+f"(c[3])
        : "r"(a[0]), "r"(a[1]), "r"(a[2]), "r"(a[3]), "r"(b[0]), "r"(b[1]));
}

__device__ __forceinline__ float round_tf32f(float x) {
    uint32_t v = __float_as_uint(x);
    asm("cvt.rna.tf32.f32 %0, %0;" : "+r"(v));
    return __uint_as_float(v);
}

// bf16 tile swizzle: [rows][32 bf16] rows of 64B, 16B chunks
__device__ __forceinline__ uint32_t swz(int row, int chunk) {
    return (uint32_t)(row * 64 + ((chunk ^ ((row >> 1) & 3)) << 4));
}
// fp32 tile swizzle: [rows][32 fp32] rows of 128B, 16B chunks
__device__ __forceinline__ uint32_t swz32(int row, int chunk) {
    return (uint32_t)(row * 128 + ((chunk ^ (row & 7)) << 4));
}

// column-group mapping for 64-wide N blocks
__device__ __forceinline__ int nmap(int bx, int tpg, int gs, int off) {
    return (bx / tpg) * gs + off + (bx % tpg) * 64;
}

// ===================== split-bf16 HMMA GEMM (128x64x32) ======================
// 256 thr, 8 warps (4M x 2N), warp tile 32x32, 3-stage, 3 CTAs/SM.
#define ATILE 8192                 // 128 x 32 bf16
#define BTILE 4096                 // 64 x 32 bf16
#define STAGEB (2 * ATILE + 2 * BTILE)  // 24576
#define NSTAGE 3
#define SMEM_MM (NSTAGE * STAGEB)  // 73728

#define OFF_AH 0
#define OFF_AL ATILE
#define OFF_BH (2 * ATILE)
#define OFF_BL (2 * ATILE + BTILE)

__global__ __launch_bounds__(256, 3)
void gemm_mma(const __nv_bfloat16* __restrict__ Ah, const __nv_bfloat16* __restrict__ Al,
              const __nv_bfloat16* __restrict__ Bh, const __nv_bfloat16* __restrict__ Bl,
              float* __restrict__ Cf, __nv_bfloat16* __restrict__ Ch,
              __nv_bfloat16* __restrict__ Cl, const float* __restrict__ bias,
              int K, int lda, int ldb, int ldc, int NH,
              size_t sAh_, size_t sAb_, size_t sBh_, size_t sBb_,
              size_t sCh_, size_t sCb_, int tpg, int gs, int noff, int round_cf)
{
    extern __shared__ char smem[];
    const uint32_t sbase = smem_u32(smem);
    const int tid = threadIdx.x, lane = tid & 31, w = tid >> 5;
    const int wm = w & 3, wn = w >> 2;  // 4 x 2 warps, warp tile 32x32

    const int z = blockIdx.z, hb = z % NH, bb = z / NH;
    const size_t offA = (size_t)hb * sAh_ + (size_t)bb * sAb_;
    const size_t offB = (size_t)hb * sBh_ + (size_t)bb * sBb_;
    const size_t offC = (size_t)hb * sCh_ + (size_t)bb * sCb_;
    const int n0 = nmap(blockIdx.x, tpg, gs, noff);

    const __nv_bfloat16* ah = Ah + offA + (size_t)(blockIdx.y * 128) * lda;
    const __nv_bfloat16* al = Al + offA + (size_t)(blockIdx.y * 128) * lda;
    const __nv_bfloat16* bh = Bh + offB + (size_t)n0 * ldb;
    const __nv_bfloat16* bl = Bl + offB + (size_t)n0 * ldb;

    float acc[2][4][4];
#pragma unroll
    for (int mt = 0; mt < 2; mt++)
#pragma unroll
        for (int j = 0; j < 4; j++)
#pragma unroll
            for (int q = 0; q < 4; q++) acc[mt][j][q] = 0.0f;

    // A: 512 chunks (2/thread); B: 256 chunks (1/thread)
    const int r0 = tid >> 2, c0 = tid & 3;
    const int r1 = r0 + 64;
    const uint32_t aso0 = swz(r0, c0), aso1 = swz(r1, c0);

    const int niter = K >> 5;

    auto issue = [&](int it) {
        const uint32_t sb = sbase + (uint32_t)(it % NSTAGE) * STAGEB;
        const int k0 = it << 5;
        const size_t ga0 = (size_t)r0 * lda + k0 + c0 * 8;
        const size_t ga1 = (size_t)r1 * lda + k0 + c0 * 8;
        const size_t gb0 = (size_t)r0 * ldb + k0 + c0 * 8;
        cp16(sb + OFF_AH + aso0, ah + ga0);
        cp16(sb + OFF_AH + aso1, ah + ga1);
        cp16(sb + OFF_AL + aso0, al + ga0);
        cp16(sb + OFF_AL + aso1, al + ga1);
        cp16(sb + OFF_BH + aso0, bh + gb0);
        cp16(sb + OFF_BL + aso0, bl + gb0);
        asm volatile("cp.async.commit_group;" ::: "memory");
    };

    issue(0);
    if (niter > 1) issue(1);

    for (int i = 0; i < niter; i++) {
        if (i + 1 < niter)
            asm volatile("cp.async.wait_group 1;" ::: "memory");
        else
            asm volatile("cp.async.wait_group 0;" ::: "memory");
        __syncthreads();
        if (i + 2 < niter) issue(i + 2);

        const uint32_t sb = sbase + (uint32_t)(i % NSTAGE) * STAGEB;
#pragma unroll
        for (int k16 = 0; k16 < 2; k16++) {
            const int rA = wm * 32 + (lane & 15);
            const int cA = k16 * 2 + (lane >> 4);
            const int rB = wn * 32 + (lane & 7) + ((lane >> 4) << 3);
            const int cB = k16 * 2 + ((lane >> 3) & 1);
            const uint32_t oA0 = swz(rA, cA), oA1 = swz(rA + 16, cA);
            const uint32_t oB0 = swz(rB, cB), oB1 = swz(rB + 16, cB);

            uint32_t a_hi[2][4], bfr[2][4];
            ldsm4(a_hi[0], sb + OFF_AH + oA0);
            ldsm4(a_hi[1], sb + OFF_AH + oA1);
            ldsm4(bfr[0],  sb + OFF_BH + oB0);
            ldsm4(bfr[1],  sb + OFF_BH + oB1);
            // hh
#pragma unroll
            for (int mt = 0; mt < 2; mt++)
#pragma unroll
                for (int nt = 0; nt < 2; nt++) {
                    mma_bf16(acc[mt][nt * 2],     a_hi[mt], &bfr[nt][0]);
                    mma_bf16(acc[mt][nt * 2 + 1], a_hi[mt], &bfr[nt][2]);
                }
            // lh (a_lo transient)
            {
                uint32_t a_lo[2][4];
                ldsm4(a_lo[0], sb + OFF_AL + oA0);
                ldsm4(a_lo[1], sb + OFF_AL + oA1);
#pragma unroll
                for (int mt = 0; mt < 2; mt++)
#pragma unroll
                    for (int nt = 0; nt < 2; nt++) {
                        mma_bf16(acc[mt][nt * 2],     a_lo[mt], &bfr[nt][0]);
                        mma_bf16(acc[mt][nt * 2 + 1], a_lo[mt], &bfr[nt][2]);
                    }
            }
            // hl (b_lo overwrites b_hi regs)
            ldsm4(bfr[0], sb + OFF_BL + oB0);
            ldsm4(bfr[1], sb + OFF_BL + oB1);
#pragma unroll
            for (int mt = 0; mt < 2; mt++)
#pragma unroll
                for (int nt = 0; nt < 2; nt++) {
                    mma_bf16(acc[mt][nt * 2],     a_hi[mt], &bfr[nt][0]);
                    mma_bf16(acc[mt][nt * 2 + 1], a_hi[mt], &bfr[nt][2]);
                }
        }
    }

    // ---------------- epilogue ----------------
    const int row0 = blockIdx.y * 128 + wm * 32;
    const int col0 = n0 + wn * 32;
#pragma unroll
    for (int mt = 0; mt < 2; mt++) {
#pragma unroll
        for (int j = 0; j < 4; j++) {
            const int r = row0 + mt * 16 + (lane >> 2);
            const int c = col0 + j * 8 + (lane & 3) * 2;
            float b0 = 0.f, b1 = 0.f;
            if (bias) { b0 = __ldg(&bias[c]); b1 = __ldg(&bias[c + 1]); }
            const float v0 = acc[mt][j][0] + b0, v1 = acc[mt][j][1] + b1;
            const float v2 = acc[mt][j][2] + b0, v3 = acc[mt][j][3] + b1;
            const size_t o0 = offC + (size_t)r * ldc + c;
            const size_t o1 = offC + (size_t)(r + 8) * ldc + c;
            if (Ch) {
                __nv_bfloat162 hh, ll;
                hh.x = __float2bfloat16(v0);
                hh.y = __float2bfloat16(v1);
                ll.x = __float2bfloat16(v0 - __bfloat162float(hh.x));
                ll.y = __float2bfloat16(v1 - __bfloat162float(hh.y));
                *(__nv_bfloat162*)(Ch + o0) = hh;
                *(__nv_bfloat162*)(Cl + o0) = ll;
                hh.x = __float2bfloat16(v2);
                hh.y = __float2bfloat16(v3);
                ll.x = __float2bfloat16(v2 - __bfloat162float(hh.x));
                ll.y = __float2bfloat16(v3 - __bfloat162float(hh.y));
                *(__nv_bfloat162*)(Ch + o1) = hh;
                *(__nv_bfloat162*)(Cl + o1) = ll;
            }
            if (Cf) {
                if (round_cf) {
                    *(float2*)(Cf + o0) = make_float2(round_tf32f(v0), round_tf32f(v1));
                    *(float2*)(Cf + o1) = make_float2(round_tf32f(v2), round_tf32f(v3));
                } else {
                    *(float2*)(Cf + o0) = make_float2(v0, v1);
                    *(float2*)(Cf + o1) = make_float2(v2, v3);
                }
            }
        }
    }
}

// ===================== tf32 GEMM (128x64x32, ldmatrix fragments) =============
// 256 thr, 8 warps (4M x 2N), warp tile 32x32, 3-stage, 3 CTAs/SM.
#define ATILE32 16384               // 128 x 32 fp32
#define BTILE32 8192                // 64 x 32 fp32
#define STAGE32 (ATILE32 + BTILE32) // 24576
#define SMEM_T32 (NSTAGE * STAGE32) // 73728

__global__ __launch_bounds__(256, 3)
void gemm_tf32(const float* __restrict__ A, const float* __restrict__ B,
               float* __restrict__ C, const float* __restrict__ bias,
               int K, int lda, int ldb, int ldc, int NH,
               size_t sAh_, size_t sAb_, size_t sBh_, size_t sBb_,
               size_t sCh_, size_t sCb_, int tpg, int gs, int noff, int round_out)
{
    extern __shared__ char smem[];
    const uint32_t sbase = smem_u32(smem);
    const int tid = threadIdx.x, lane = tid & 31, w = tid >> 5;
    const int wm = w & 3, wn = w >> 2;

    const int z = blockIdx.z, hb = z % NH, bb = z / NH;
    const size_t offA = (size_t)hb * sAh_ + (size_t)bb * sAb_;
    const size_t offB = (size_t)hb * sBh_ + (size_t)bb * sBb_;
    const size_t offC = (size_t)hb * sCh_ + (size_t)bb * sCb_;
    const int n0 = nmap(blockIdx.x, tpg, gs, noff);

    const float* ag = A + offA + (size_t)(blockIdx.y * 128) * lda;
    const float* bg = B + offB + (size_t)n0 * ldb;

    float acc[2][4][4];
#pragma unroll
    for (int mt = 0; mt < 2; mt++)
#pragma unroll
        for (int j = 0; j < 4; j++)
#pragma unroll
            for (int q = 0; q < 4; q++) acc[mt][j][q] = 0.0f;

    const int niter = K >> 5;

    auto issue = [&](int it) {
        const uint32_t sb = sbase + (uint32_t)(it % NSTAGE) * STAGE32;
        const int k0 = it << 5;
        // A: 1024 chunks -> 4/thread
#pragma unroll
        for (int q = 0; q < 4; q++) {
            const int idx = tid + q * 256;
            const int r = idx >> 3, c = idx & 7;
            cp16(sb + swz32(r, c), ag + (size_t)r * lda + k0 + c * 4);
        }
        // B: 512 chunks -> 2/thread
#pragma unroll
        for (int q = 0; q < 2; q++) {
            const int idx = tid + q * 256;
            const int r = idx >> 3, c = idx & 7;
            cp16(sb + ATILE32 + swz32(r, c), bg + (size_t)r * ldb + k0 + c * 4);
        }
        asm volatile("cp.async.commit_group;" ::: "memory");
    };

    issue(0);
    if (niter > 1) issue(1);

    const int frow = lane & 15;
    const int fch  = lane >> 4;

    for (int i = 0; i < niter; i++) {
        if (i + 1 < niter)
            asm volatile("cp.async.wait_group 1;" ::: "memory");
        else
            asm volatile("cp.async.wait_group 0;" ::: "memory");
        __syncthreads();
        if (i + 2 < niter) issue(i + 2);

        const uint32_t sb = sbase + (uint32_t)(i % NSTAGE) * STAGE32;
        const uint32_t sbB = sb + ATILE32;
#pragma unroll
        for (int ks = 0; ks < 4; ks++) {
            const int ch = 2 * ks + fch;
            uint32_t af[2][4], bf[4][2];
            ldsm4(af[0], sb + swz32(wm * 32 + frow, ch));
            ldsm4(af[1], sb + swz32(wm * 32 + 16 + frow, ch));
#pragma unroll
            for (int np = 0; np < 2; np++) {
                uint32_t tmp[4];
                ldsm4(tmp, sbB + swz32(wn * 32 + np * 16 + frow, ch));
                bf[2 * np][0]     = tmp[0];
                bf[2 * np + 1][0] = tmp[1];
                bf[2 * np][1]     = tmp[2];
                bf[2 * np + 1][1] = tmp[3];
            }
#pragma unroll
            for (int mt = 0; mt < 2; mt++)
#pragma unroll
                for (int nt = 0; nt < 4; nt++)
                    mma_tf32(acc[mt][nt], af[mt], bf[nt]);
        }
    }

    // ---------------- epilogue ----------------
    const int gid = lane >> 2, tig = lane & 3;
    const int row0 = blockIdx.y * 128 + wm * 32;
    const int col0 = n0 + wn * 32;
#pragma unroll
    for (int mt = 0; mt < 2; mt++) {
#pragma unroll
        for (int j = 0; j < 4; j++) {
            const int r = row0 + mt * 16 + gid;
            const int c = col0 + j * 8 + tig * 2;
            float b0 = 0.f, b1 = 0.f;
            if (bias) { b0 = __ldg(&bias[c]); b1 = __ldg(&bias[c + 1]); }
            float v0 = acc[mt][j][0] + b0, v1 = acc[mt][j][1] + b1;
            float v2 = acc[mt][j][2] + b0, v3 = acc[mt][j][3] + b1;
            if (round_out) {
                v0 = round_tf32f(v0); v1 = round_tf32f(v1);
                v2 = round_tf32f(v2); v3 = round_tf32f(v3);
            }
            const size_t o0 = offC + (size_t)r * ldc + c;
            const size_t o1 = offC + (size_t)(r + 8) * ldc + c;
            *(float2*)(C + o0) = make_float2(v0, v1);
            *(float2*)(C + o1) = make_float2(v2, v3);
        }
    }
}

// ===================== aux kernels ===========================================
__global__ void split2(const float* __restrict__ x, __nv_bfloat16* __restrict__ h,
                       __nv_bfloat16* __restrict__ l, size_t n)
{
    size_t i = (size_t)blockIdx.x * blockDim.x + threadIdx.x;
    const size_t stride = (size_t)gridDim.x * blockDim.x;
    for (; i < n; i += stride) {
        float v = x[i];
        __nv_bfloat16 hi = __float2bfloat16(v);
        h[i] = hi;
        l[i] = __float2bfloat16(v - __bfloat162float(hi));
    }
}

__global__ void round_copy_tf32(const float* __restrict__ in,
                                float* __restrict__ out, size_t n)
{
    size_t i = (size_t)blockIdx.x * blockDim.x + threadIdx.x;
    const size_t stride = (size_t)gridDim.x * blockDim.x;
    for (; i < n; i += stride)
        out[i] = round_tf32f(in[i]);
}

__global__ void softmax_split(const float* __restrict__ sc,
                              __nv_bfloat16* __restrict__ ph,
                              __nv_bfloat16* __restrict__ pl, float scale)
{
    const int tid = threadIdx.x;
    const size_t base = (size_t)blockIdx.x * 2048;
    const float* p = sc + base;
    __shared__ float red[256];

    float v[8];
    float mx = -1e30f;
#pragma unroll
    for (int i = 0; i < 8; i++) {
        v[i] = p[tid + i * 256] * scale;
        mx = fmaxf(mx, v[i]);
    }
    red[tid] = mx;
    __syncthreads();
#pragma unroll
    for (int s = 128; s > 0; s >>= 1) {
        if (tid < s) red[tid] = fmaxf(red[tid], red[tid + s]);
        __syncthreads();
    }
    mx = red[0];
    __syncthreads();

    float sum = 0.0f;
#pragma unroll
    for (int i = 0; i < 8; i++) {
        v[i] = __expf(v[i] - mx);
        sum += v[i];
    }
    red[tid] = sum;
    __syncthreads();
#pragma unroll
    for (int s = 128; s > 0; s >>= 1) {
        if (tid < s) red[tid] += red[tid + s];
        __syncthreads();
    }
    const float inv = 1.0f / red[0];
#pragma unroll
    for (int i = 0; i < 8; i++) {
        float pv = v[i] * inv;
        __nv_bfloat16 hi = __float2bfloat16(pv);
        ph[base + tid + i * 256] = hi;
        pl[base + tid + i * 256] = __float2bfloat16(pv - __bfloat162float(hi));
    }
}

// V^T per (b,h): Vt[d][sk] = h2[(b,sk)][h*1536+1024+d]  (hi and lo)
__global__ void transpose_split_v(const __nv_bfloat16* __restrict__ h2h,
                                  const __nv_bfloat16* __restrict__ h2l,
                                  __nv_bfloat16* __restrict__ vth,
                                  __nv_bfloat16* __restrict__ vtl)
{
    __shared__ __nv_bfloat16 th[32][33], tl[32][33];
    const int z = blockIdx.z, b = z >> 3, h = z & 7;
    const int sk0 = blockIdx.x * 32, d0 = blockIdx.y * 32;
    const int tx = threadIdx.x, ty = threadIdx.y;  // 32 x 8
    const size_t srcbase = (size_t)b * 2048 * 12288 + h * 1536 + 1024;
#pragma unroll
    for (int j = 0; j < 4; j++) {
        int sk = sk0 + ty + j * 8;
        size_t s = srcbase + (size_t)sk * 12288 + d0 + tx;
        th[ty + j * 8][tx] = h2h[s];
        tl[ty + j * 8][tx] = h2l[s];
    }
    __syncthreads();
    const size_t dstbase = (size_t)(b * 8 + h) * 512 * 2048;
#pragma unroll
    for (int j = 0; j < 4; j++) {
        int d = d0 + ty + j * 8;
        size_t o = dstbase + (size_t)d * 2048 + sk0 + tx;
        vth[o] = th[tx][ty + j * 8];
        vtl[o] = tl[tx][ty + j * 8];
    }
}

// =============================================================================
extern "C" void kernel_launch(void* const* d_in, const int* in_sizes, int n_in,
                              void* d_out, int out_size)
{
    const float* x     = (const float*)d_in[0];
    const float* W_sep = (const float*)d_in[1];
    const float* b_sep = (const float*)d_in[2];
    const float* W_mul = (const float*)d_in[3];
    const float* b_mul = (const float*)d_in[4];
    const float* W_res = (const float*)d_in[5];
    const float* b_res = (const float*)d_in[6];
    float* out = (float*)d_out;

    __nv_bfloat16 *xh, *xl, *Wsh, *Wsl, *Wmh, *Wml, *Wrh, *Wrl;
    __nv_bfloat16 *h1h, *h1l, *h2h, *h2l, *Ph, *Pl, *Vth, *Vtl, *aph, *apl;
    float *sc, *h1f, *h2f, *Wmf;
    cudaGetSymbolAddress((void**)&xh,  g_xh);  cudaGetSymbolAddress((void**)&xl,  g_xl);
    cudaGetSymbolAddress((void**)&Wsh, g_Wsh); cudaGetSymbolAddress((void**)&Wsl, g_Wsl);
    cudaGetSymbolAddress((void**)&Wmh, g_Wmh); cudaGetSymbolAddress((void**)&Wml, g_Wml);
    cudaGetSymbolAddress((void**)&Wrh, g_Wrh); cudaGetSymbolAddress((void**)&Wrl, g_Wrl);
    cudaGetSymbolAddress((void**)&h1h, g_h1h); cudaGetSymbolAddress((void**)&h1l, g_h1l);
    cudaGetSymbolAddress((void**)&h2h, g_h2h); cudaGetSymbolAddress((void**)&h2l, g_h2l);
    cudaGetSymbolAddress((void**)&Ph,  g_Ph);  cudaGetSymbolAddress((void**)&Pl,  g_Pl);
    cudaGetSymbolAddress((void**)&Vth, g_Vth); cudaGetSymbolAddress((void**)&Vtl, g_Vtl);
    cudaGetSymbolAddress((void**)&aph, g_aph); cudaGetSymbolAddress((void**)&apl, g_apl);
    cudaGetSymbolAddress((void**)&sc,  g_sc);
    cudaGetSymbolAddress((void**)&h1f, g_h1f);
    cudaGetSymbolAddress((void**)&h2f, g_h2f);
    cudaGetSymbolAddress((void**)&Wmf, g_Wmf);

    cudaFuncSetAttribute(gemm_mma,  cudaFuncAttributeMaxDynamicSharedMemorySize, SMEM_MM);
    cudaFuncSetAttribute(gemm_tf32, cudaFuncAttributeMaxDynamicSharedMemorySize, SMEM_T32);

    const size_t S = 2048, D = 512, H = 8;

    // splits / rounding
    split2<<<1024, 256>>>(x,     xh,  xl,  4096UL * 512);
    split2<<<1024, 256>>>(W_sep, Wsh, Wsl, 1536UL * 512);
    round_copy_tf32<<<2048, 256>>>(W_mul, Wmf, 12288UL * 1536);

    // GEMM1 (bf16-split): h1 = x @ W_sep^T + b_sep; h1f written tf32-rounded
    gemm_mma<<<dim3(24, 32, 1), 256, SMEM_MM>>>(
        xh, xl, Wsh, Wsl, h1f, h1h, h1l, b_sep,
        512, 512, 512, 1536, 1, 0, 0, 0, 0, 0, 0, 24, 0, 0, 1);

    // GEMM2a (tf32): Q,K columns (1024 per 1536 group) -> h2f (tf32-rounded)
    gemm_tf32<<<dim3(128, 32, 1), 256, SMEM_T32>>>(
        h1f, Wmf, h2f, b_mul,
        1536, 1536, 1536, 12288, 1, 0, 0, 0, 0, 0, 0, 16, 1536, 0, 1);

    // QK^T (tf32) batched: sc = Q @ K^T
    gemm_tf32<<<dim3(32, 16, 16), 256, SMEM_T32>>>(
        h2f, h2f + 512, sc, nullptr,
        512, 12288, 12288, 2048, 8,
        1536, S * 12288, 1536, S * 12288,
        S * S, H * S * S, 32, 0, 0, 0);

    // split W_mul for V-column pass
    split2<<<2048, 256>>>(W_mul, Wmh, Wml, 12288UL * 1536);

    // GEMM2b (bf16-split): V columns (512 per 1536 group) -> h2h/h2l
    gemm_mma<<<dim3(64, 32, 1), 256, SMEM_MM>>>(
        h1h, h1l, Wmh, Wml, nullptr, h2h, h2l, b_mul,
        1536, 1536, 1536, 12288, 1, 0, 0, 0, 0, 0, 0, 8, 1536, 1024, 0);

    // softmax(scale * sc) -> P hi/lo
    softmax_split<<<16 * 2048, 256>>>(sc, Ph, Pl, 1.0f / sqrtf(512.0f));

    // V^T split
    transpose_split_v<<<dim3(64, 16, 16), dim3(32, 8)>>>(h2h, h2l, Vth, Vtl);

    // PV (bf16-split): ap = P @ Vt^T
    gemm_mma<<<dim3(8, 16, 16), 256, SMEM_MM>>>(
        Ph, Pl, Vth, Vtl, nullptr, aph, apl, nullptr,
        2048, 2048, 2048, 4096, 8,
        S * S, H * S * S, D * S, H * D * S,
        512, S * 4096, 8, 0, 0, 0);

    // split W_res
    split2<<<1024, 256>>>(W_res, Wrh, Wrl, 512UL * 4096);

    // GEMM3 (bf16-split): out = ap @ W_res^T + b_res
    gemm_mma<<<dim3(8, 32, 1), 256, SMEM_MM>>>(
        aph, apl, Wrh, Wrl, out, nullptr, nullptr, b_res,
        4096, 4096, 4096, 512, 1, 0, 0, 0, 0, 0, 0, 8, 0, 0, 0);
}

// round 10
// speedup vs baseline: 1.2306x; 1.2306x over previous
#include <cuda_runtime.h>
#include <cuda_bf16.h>
#include <math.h>
#include <stdint.h>

// ===================== scratch (static device arrays) ========================
__device__ float g_xf [4096UL * 512];
__device__ float g_Wsf[1536UL * 512];
__device__ float g_Wmf[12288UL * 1536];
__device__ float g_Wrf[512UL * 4096];
__device__ float g_h1f[4096UL * 1536];
__device__ float g_h2f[4096UL * 12288];
__device__ float g_sc [16UL * 2048 * 2048];
__device__ float g_Pf [16UL * 2048 * 2048];
__device__ float g_Vtf[16UL * 512 * 2048];
__device__ float g_apf[4096UL * 4096];

// ===================== helpers (base-target PTX only) ========================
__device__ __forceinline__ uint32_t smem_u32(const void* p) {
    uint32_t a;
    asm("{ .reg .u64 t; cvta.to.shared.u64 t, %1; cvt.u32.u64 %0, t; }"
        : "=r"(a) : "l"(p));
    return a;
}

__device__ __forceinline__ void cp16(uint32_t s, const void* g) {
    asm volatile("cp.async.cg.shared.global [%0], [%1], 16;"
                 :: "r"(s), "l"(g) : "memory");
}

__device__ __forceinline__ void ldsm4(uint32_t* r, uint32_t addr) {
    asm volatile("ldmatrix.sync.aligned.m8n8.x4.shared.b16 {%0,%1,%2,%3}, [%4];"
                 : "=r"(r[0]), "=r"(r[1]), "=r"(r[2]), "=r"(r[3]) : "r"(addr));
}

__device__ __forceinline__ void mma_tf32(float* c, const uint32_t* a, const uint32_t* b) {
    asm volatile(
        "mma.sync.aligned.m16n8k8.row.col.f32.tf32.tf32.f32 "
        "{%0,%1,%2,%3}, {%4,%5,%6,%7}, {%8,%9}, {%0,%1,%2,%3};"
        : "+f"(c[0]), "+f"(c[1]), "+f"(c[2]), "+f"(c[3])
        : "r"(a[0]), "r"(a[1]), "r"(a[2]), "r"(a[3]), "r"(b[0]), "r"(b[1]));
}

__device__ __forceinline__ float round_tf32f(float x) {
    uint32_t v = __float_as_uint(x);
    asm("cvt.rna.tf32.f32 %0, %0;" : "+r"(v));
    return __uint_as_float(v);
}

// fp32 tile swizzle: [rows][32 fp32] rows of 128B, 16B chunks
__device__ __forceinline__ uint32_t swz32(int row, int chunk) {
    return (uint32_t)(row * 128 + ((chunk ^ (row & 7)) << 4));
}

// ===================== tf32 GEMM (128x128x32, ldmatrix fragments) ============
// C = A @ B^T. A: M x K (lda), B: N x K (ldb), fp32 already tf32-rounded.
// 256 thr, 8 warps (4M x 2N), warp tile 32x64, 3-stage, 2 CTAs/SM.
#define ATILE32 16384               // 128 x 32 fp32
#define STAGE32 (2 * ATILE32)       // 32768
#define NSTAGE 3
#define SMEM_T32 (NSTAGE * STAGE32) // 98304

__global__ __launch_bounds__(256, 2)
void gemm_tf32(const float* __restrict__ A, const float* __restrict__ B,
               float* __restrict__ C, const float* __restrict__ bias,
               int K, int lda, int ldb, int ldc, int NH,
               size_t sAh_, size_t sAb_, size_t sBh_, size_t sBb_,
               size_t sCh_, size_t sCb_, int round_out)
{
    extern __shared__ char smem[];
    const uint32_t sbase = smem_u32(smem);
    const int tid = threadIdx.x, lane = tid & 31, w = tid >> 5;
    const int wm = w & 3, wn = w >> 2;  // 4M x 2N warps, warp tile 32x64

    const int z = blockIdx.z, hb = z % NH, bb = z / NH;
    const size_t offA = (size_t)hb * sAh_ + (size_t)bb * sAb_;
    const size_t offB = (size_t)hb * sBh_ + (size_t)bb * sBb_;
    const size_t offC = (size_t)hb * sCh_ + (size_t)bb * sCb_;
    const int n0 = blockIdx.x * 128;

    const float* ag = A + offA + (size_t)(blockIdx.y * 128) * lda;
    const float* bg = B + offB + (size_t)n0 * ldb;

    float acc[2][8][4];
#pragma unroll
    for (int mt = 0; mt < 2; mt++)
#pragma unroll
        for (int j = 0; j < 8; j++)
#pragma unroll
            for (int q = 0; q < 4; q++) acc[mt][j][q] = 0.0f;

    const int niter = K >> 5;

    auto issue = [&](int it) {
        const uint32_t sb = sbase + (uint32_t)(it % NSTAGE) * STAGE32;
        const int k0 = it << 5;
        // A and B: 1024 chunks each -> 4/thread each
#pragma unroll
        for (int q = 0; q < 4; q++) {
            const int idx = tid + q * 256;
            const int r = idx >> 3, c = idx & 7;
            const uint32_t so = swz32(r, c);
            cp16(sb + so,           ag + (size_t)r * lda + k0 + c * 4);
            cp16(sb + ATILE32 + so, bg + (size_t)r * ldb + k0 + c * 4);
        }
        asm volatile("cp.async.commit_group;" ::: "memory");
    };

    issue(0);
    if (niter > 1) issue(1);

    const int frow = lane & 15;
    const int fch  = lane >> 4;

    for (int i = 0; i < niter; i++) {
        if (i + 1 < niter)
            asm volatile("cp.async.wait_group 1;" ::: "memory");
        else
            asm volatile("cp.async.wait_group 0;" ::: "memory");
        __syncthreads();
        if (i + 2 < niter) issue(i + 2);

        const uint32_t sb = sbase + (uint32_t)(i % NSTAGE) * STAGE32;
        const uint32_t sbB = sb + ATILE32;
#pragma unroll
        for (int ks = 0; ks < 4; ks++) {
            const int ch = 2 * ks + fch;
            uint32_t af[2][4], bf[8][2];
            ldsm4(af[0], sb + swz32(wm * 32 + frow, ch));
            ldsm4(af[1], sb + swz32(wm * 32 + 16 + frow, ch));
#pragma unroll
            for (int np = 0; np < 4; np++) {
                uint32_t tmp[4];
                ldsm4(tmp, sbB + swz32(wn * 64 + np * 16 + frow, ch));
                bf[2 * np][0]     = tmp[0];
                bf[2 * np + 1][0] = tmp[1];
                bf[2 * np][1]     = tmp[2];
                bf[2 * np + 1][1] = tmp[3];
            }
#pragma unroll
            for (int mt = 0; mt < 2; mt++)
#pragma unroll
                for (int nt = 0; nt < 8; nt++)
                    mma_tf32(acc[mt][nt], af[mt], bf[nt]);
        }
    }

    // ---------------- epilogue ----------------
    const int gid = lane >> 2, tig = lane & 3;
    const int row0 = blockIdx.y * 128 + wm * 32;
    const int col0 = n0 + wn * 64;
#pragma unroll
    for (int mt = 0; mt < 2; mt++) {
#pragma unroll
        for (int j = 0; j < 8; j++) {
            const int r = row0 + mt * 16 + gid;
            const int c = col0 + j * 8 + tig * 2;
            float b0 = 0.f, b1 = 0.f;
            if (bias) { b0 = __ldg(&bias[c]); b1 = __ldg(&bias[c + 1]); }
            float v0 = acc[mt][j][0] + b0, v1 = acc[mt][j][1] + b1;
            float v2 = acc[mt][j][2] + b0, v3 = acc[mt][j][3] + b1;
            if (round_out) {
                v0 = round_tf32f(v0); v1 = round_tf32f(v1);
                v2 = round_tf32f(v2); v3 = round_tf32f(v3);
            }
            const size_t o0 = offC + (size_t)r * ldc + c;
            const size_t o1 = offC + (size_t)(r + 8) * ldc + c;
            *(float2*)(C + o0) = make_float2(v0, v1);
            *(float2*)(C + o1) = make_float2(v2, v3);
        }
    }
}

// ===================== aux kernels ===========================================
__global__ void round_copy_tf32(const float* __restrict__ in,
                                float* __restrict__ out, size_t n)
{
    size_t i = ((size_t)blockIdx.x * blockDim.x + threadIdx.x) * 4;
    const size_t stride = (size_t)gridDim.x * blockDim.x * 4;
    for (; i < n; i += stride) {
        float4 v = *(const float4*)(in + i);
        v.x = round_tf32f(v.x); v.y = round_tf32f(v.y);
        v.z = round_tf32f(v.z); v.w = round_tf32f(v.w);
        *(float4*)(out + i) = v;
    }
}

__global__ void softmax_tf32(const float* __restrict__ sc,
                             float* __restrict__ pf, float scale)
{
    const int tid = threadIdx.x;
    const size_t base = (size_t)blockIdx.x * 2048;
    const float* p = sc + base;
    __shared__ float red[256];

    float v[8];
    float mx = -1e30f;
#pragma unroll
    for (int i = 0; i < 8; i++) {
        v[i] = p[tid + i * 256] * scale;
        mx = fmaxf(mx, v[i]);
    }
    red[tid] = mx;
    __syncthreads();
#pragma unroll
    for (int s = 128; s > 0; s >>= 1) {
        if (tid < s) red[tid] = fmaxf(red[tid], red[tid + s]);
        __syncthreads();
    }
    mx = red[0];
    __syncthreads();

    float sum = 0.0f;
#pragma unroll
    for (int i = 0; i < 8; i++) {
        v[i] = __expf(v[i] - mx);
        sum += v[i];
    }
    red[tid] = sum;
    __syncthreads();
#pragma unroll
    for (int s = 128; s > 0; s >>= 1) {
        if (tid < s) red[tid] += red[tid + s];
        __syncthreads();
    }
    const float inv = 1.0f / red[0];
#pragma unroll
    for (int i = 0; i < 8; i++)
        pf[base + tid + i * 256] = round_tf32f(v[i] * inv);
}

// V^T per (b,h): Vt[d][sk] = h2f[(b,sk)][h*1536+1024+d]  (already tf32-rounded)
__global__ void transpose_v(const float* __restrict__ h2f,
                            float* __restrict__ vtf)
{
    __shared__ float t[32][33];
    const int z = blockIdx.z, b = z >> 3, h = z & 7;
    const int sk0 = blockIdx.x * 32, d0 = blockIdx.y * 32;
    const int tx = threadIdx.x, ty = threadIdx.y;  // 32 x 8
    const size_t srcbase = (size_t)b * 2048 * 12288 + h * 1536 + 1024;
#pragma unroll
    for (int j = 0; j < 4; j++) {
        int sk = sk0 + ty + j * 8;
        t[ty + j * 8][tx] = h2f[srcbase + (size_t)sk * 12288 + d0 + tx];
    }
    __syncthreads();
    const size_t dstbase = (size_t)(b * 8 + h) * 512 * 2048;
#pragma unroll
    for (int j = 0; j < 4; j++) {
        int d = d0 + ty + j * 8;
        vtf[dstbase + (size_t)d * 2048 + sk0 + tx] = t[tx][ty + j * 8];
    }
}

// =============================================================================
extern "C" void kernel_launch(void* const* d_in, const int* in_sizes, int n_in,
                              void* d_out, int out_size)
{
    const float* x     = (const float*)d_in[0];
    const float* W_sep = (const float*)d_in[1];
    const float* b_sep = (const float*)d_in[2];
    const float* W_mul = (const float*)d_in[3];
    const float* b_mul = (const float*)d_in[4];
    const float* W_res = (const float*)d_in[5];
    const float* b_res = (const float*)d_in[6];
    float* out = (float*)d_out;

    float *xf, *Wsf, *Wmf, *Wrf, *h1f, *h2f, *sc, *Pf, *Vtf, *apf;
    cudaGetSymbolAddress((void**)&xf,  g_xf);
    cudaGetSymbolAddress((void**)&Wsf, g_Wsf);
    cudaGetSymbolAddress((void**)&Wmf, g_Wmf);
    cudaGetSymbolAddress((void**)&Wrf, g_Wrf);
    cudaGetSymbolAddress((void**)&h1f, g_h1f);
    cudaGetSymbolAddress((void**)&h2f, g_h2f);
    cudaGetSymbolAddress((void**)&sc,  g_sc);
    cudaGetSymbolAddress((void**)&Pf,  g_Pf);
    cudaGetSymbolAddress((void**)&Vtf, g_Vtf);
    cudaGetSymbolAddress((void**)&apf, g_apf);

    cudaFuncSetAttribute(gemm_tf32, cudaFuncAttributeMaxDynamicSharedMemorySize, SMEM_T32);

    const size_t S = 2048, D = 512, H = 8;

    // tf32-round inputs & weights
    round_copy_tf32<<<512,  256>>>(x,     xf,  4096UL * 512);
    round_copy_tf32<<<512,  256>>>(W_sep, Wsf, 1536UL * 512);
    round_copy_tf32<<<2048, 256>>>(W_mul, Wmf, 12288UL * 1536);

    // GEMM1: h1 = x @ W_sep^T + b_sep   [4096 x 1536], K=512 (out tf32-rounded)
    gemm_tf32<<<dim3(12, 32, 1), 256, SMEM_T32>>>(
        xf, Wsf, h1f, b_sep,
        512, 512, 512, 1536, 1, 0, 0, 0, 0, 0, 0, 1);

    // GEMM2: h2 = h1 @ W_mul^T + b_mul  [4096 x 12288], K=1536 (out tf32-rounded)
    gemm_tf32<<<dim3(96, 32, 1), 256, SMEM_T32>>>(
        h1f, Wmf, h2f, b_mul,
        1536, 1536, 1536, 12288, 1, 0, 0, 0, 0, 0, 0, 1);

    // QK^T batched (z = b*8 + h): sc = Q @ K^T  [2048 x 2048], K=512
    gemm_tf32<<<dim3(16, 16, 16), 256, SMEM_T32>>>(
        h2f, h2f + 512, sc, nullptr,
        512, 12288, 12288, 2048, 8,
        1536, S * 12288, 1536, S * 12288,
        S * S, H * S * S, 0);

    // softmax(scale * sc) -> P (tf32-rounded fp32)
    softmax_tf32<<<16 * 2048, 256>>>(sc, Pf, 1.0f / sqrtf(512.0f));

    // V^T (values already tf32-rounded in h2f)
    transpose_v<<<dim3(64, 16, 16), dim3(32, 8)>>>(h2f, Vtf);

    round_copy_tf32<<<512, 256>>>(W_res, Wrf, 512UL * 4096);

    // PV batched: ap[b, sq, h*512+d] = P @ Vt^T  [2048 x 512], K=2048 (rounded)
    gemm_tf32<<<dim3(4, 16, 16), 256, SMEM_T32>>>(
        Pf, Vtf, apf, nullptr,
        2048, 2048, 2048, 4096, 8,
        S * S, H * S * S, D * S, H * D * S,
        512, S * 4096, 1);

    // GEMM3: out = ap @ W_res^T + b_res  [4096 x 512], K=4096
    gemm_tf32<<<dim3(4, 32, 1), 256, SMEM_T32>>>(
        apf, Wrf, out, b_res,
        4096, 4096, 4096, 512, 1, 0, 0, 0, 0, 0, 0, 0);
}